// round 1
// baseline (speedup 1.0000x reference)
#include <cuda_runtime.h>
#include <math.h>

#define BB 4
#define TT 4096
#define DD 32
#define SPLITS 8
#define CHUNK 512      // TT / SPLITS
#define MTILE 64       // query rows per CTA
#define NKEY 64        // key rows per smem tile

// Scratch (no cudaMalloc allowed): q,k,v + partial outputs/stats
__device__ float g_q[BB * TT * DD];
__device__ float g_k[BB * TT * DD];
__device__ float g_v[BB * TT * DD];
__device__ float g_po[BB * SPLITS * TT * DD];   // partial o (unnormalized)
__device__ float g_pml[BB * SPLITS * TT * 2];   // partial (m, l)

// ---------------------------------------------------------------------------
// Kernel 1: QKV projection.  q/k/v[b,t,h] = sum_n x[b,t,n] * W[h,n]
// 256 threads = 8 warps; warp -> one row t, lane -> h.
// ---------------------------------------------------------------------------
__global__ void __launch_bounds__(256) qkv_kernel(const float* __restrict__ x,
                                                  const float* __restrict__ Wq,
                                                  const float* __restrict__ Wk,
                                                  const float* __restrict__ Wv) {
    __shared__ float swq[DD * DD], swk[DD * DD], swv[DD * DD];  // transposed [n][h]
    const int tid = threadIdx.x;
    for (int idx = tid; idx < DD * DD; idx += 256) {
        int h = idx >> 5, n = idx & 31;
        swq[n * DD + h] = Wq[idx];
        swk[n * DD + h] = Wk[idx];
        swv[n * DD + h] = Wv[idx];
    }
    __syncthreads();

    const int warp = tid >> 5, lane = tid & 31;
    const int row = blockIdx.x * 8 + warp;   // 0 .. BB*TT-1
    const float xv = x[row * DD + lane];

    float q = 0.f, k = 0.f, v = 0.f;
#pragma unroll
    for (int n = 0; n < DD; n++) {
        float xn = __shfl_sync(0xffffffffu, xv, n);
        q = fmaf(xn, swq[n * DD + lane], q);
        k = fmaf(xn, swk[n * DD + lane], k);
        v = fmaf(xn, swv[n * DD + lane], v);
    }
    g_q[row * DD + lane] = q;
    g_k[row * DD + lane] = k;
    g_v[row * DD + lane] = v;
}

// ---------------------------------------------------------------------------
// Kernel 2: partial flash attention over one KV chunk (split-KV).
// grid = (64 query tiles, SPLITS, BB); 64 threads; thread -> one query row.
// ---------------------------------------------------------------------------
#define DOT4(qq, kk) (fmaf((qq).x, (kk).x, fmaf((qq).y, (kk).y, fmaf((qq).z, (kk).z, (qq).w * (kk).w))))
#define OSCALE(oo)  { (oo).x *= c; (oo).y *= c; (oo).z *= c; (oo).w *= c; }
#define PVACC(oo, vv) { (oo).x = fmaf(p, (vv).x, (oo).x); (oo).y = fmaf(p, (vv).y, (oo).y); \
                        (oo).z = fmaf(p, (vv).z, (oo).z); (oo).w = fmaf(p, (vv).w, (oo).w); }
#define QSC(qq)     { (qq).x *= SCALE; (qq).y *= SCALE; (qq).z *= SCALE; (qq).w *= SCALE; }

__global__ void __launch_bounds__(64) attn_partial_kernel() {
    const int i  = blockIdx.x;   // query tile
    const int sp = blockIdx.y;   // kv split
    const int b  = blockIdx.z;
    if (sp * 8 > i) return;      // chunk entirely above the diagonal

    const int tid = threadIdx.x;
    const int tq  = i * MTILE + tid;

    __shared__ float4 Ks[NKEY * 8];
    __shared__ float4 Vs[NKEY * 8];

    const float SCALE = 0.17677669529663687f;   // 32^-0.5
    const float4* qg = (const float4*)(g_q + (b * TT + tq) * DD);
    float4 q0 = qg[0], q1 = qg[1], q2 = qg[2], q3 = qg[3];
    float4 q4 = qg[4], q5 = qg[5], q6 = qg[6], q7 = qg[7];
    QSC(q0) QSC(q1) QSC(q2) QSC(q3) QSC(q4) QSC(q5) QSC(q6) QSC(q7)

    const float4 z = make_float4(0.f, 0.f, 0.f, 0.f);
    float4 o0 = z, o1 = z, o2 = z, o3 = z, o4 = z, o5 = z, o6 = z, o7 = z;
    float m = -INFINITY, l = 0.f;

    const int nk = min(8, i - sp * 8 + 1);   // key tiles in this chunk (causal)
    const float4* Kg = (const float4*)(g_k + (b * TT + sp * CHUNK) * DD);
    const float4* Vg = (const float4*)(g_v + (b * TT + sp * CHUNK) * DD);

    for (int jt = 0; jt < nk; jt++) {
        if (jt) __syncthreads();
#pragma unroll
        for (int u = 0; u < 8; u++) {
            Ks[tid + 64 * u] = Kg[jt * 512 + tid + 64 * u];
            Vs[tid + 64 * u] = Vg[jt * 512 + tid + 64 * u];
        }
        __syncthreads();

        const int ktbase = sp * CHUNK + jt * NKEY;
        const int lim = min(NKEY, tq - ktbase + 1);   // >= 1 by construction
        for (int n = 0; n < lim; n++) {
            const float4* kr = Ks + n * 8;
            float4 k0 = kr[0], k1 = kr[1], k2 = kr[2], k3 = kr[3];
            float4 k4 = kr[4], k5 = kr[5], k6 = kr[6], k7 = kr[7];
            float sc = ((DOT4(q0, k0) + DOT4(q1, k1)) + (DOT4(q2, k2) + DOT4(q3, k3)))
                     + ((DOT4(q4, k4) + DOT4(q5, k5)) + (DOT4(q6, k6) + DOT4(q7, k7)));
            // Reference quirk: tril(wei) then mask entries == 0 -> -inf.
            if (sc != 0.0f) {
                if (sc > m) {
                    float c = __expf(m - sc);   // exp(-inf)=0 handles first key
                    m = sc;
                    l *= c;
                    OSCALE(o0) OSCALE(o1) OSCALE(o2) OSCALE(o3)
                    OSCALE(o4) OSCALE(o5) OSCALE(o6) OSCALE(o7)
                }
                float p = __expf(sc - m);
                l += p;
                const float4* vr = Vs + n * 8;
                float4 v0 = vr[0], v1 = vr[1], v2 = vr[2], v3 = vr[3];
                float4 v4 = vr[4], v5 = vr[5], v6 = vr[6], v7 = vr[7];
                PVACC(o0, v0) PVACC(o1, v1) PVACC(o2, v2) PVACC(o3, v3)
                PVACC(o4, v4) PVACC(o5, v5) PVACC(o6, v6) PVACC(o7, v7)
            }
        }
    }

    const int pidx = (b * SPLITS + sp) * TT + tq;
    g_pml[2 * pidx]     = m;
    g_pml[2 * pidx + 1] = l;
    float4* po = (float4*)(g_po + pidx * DD);
    po[0] = o0; po[1] = o1; po[2] = o2; po[3] = o3;
    po[4] = o4; po[5] = o5; po[6] = o6; po[7] = o7;
}

// ---------------------------------------------------------------------------
// Kernel 3: combine partial states across splits.
// 128 threads = 4 warps; warp -> one row, lane -> d.
// ---------------------------------------------------------------------------
__global__ void __launch_bounds__(128) attn_combine_kernel(float* __restrict__ out) {
    const int tid = threadIdx.x;
    const int warp = tid >> 5, lane = tid & 31;
    const int row = blockIdx.x * 4 + warp;      // 0 .. BB*TT-1
    const int b = row / TT, t = row % TT;
    const int nS = t / CHUNK + 1;

    float M = -INFINITY, L = 0.f, acc = 0.f;
    const float2* pml2 = (const float2*)g_pml;
#pragma unroll 4
    for (int s2 = 0; s2 < nS; s2++) {
        const int pidx = (b * SPLITS + s2) * TT + t;
        float2 ml = pml2[pidx];
        if (ml.y == 0.0f) continue;            // split contributed nothing
        float os = g_po[pidx * DD + lane];
        if (ml.x > M) {
            float c = __expf(M - ml.x);
            L *= c; acc *= c; M = ml.x;
        }
        float w = __expf(ml.x - M);
        L   = fmaf(w, ml.y, L);
        acc = fmaf(w, os, acc);
    }
    out[row * DD + lane] = acc / L;
}

// ---------------------------------------------------------------------------
extern "C" void kernel_launch(void* const* d_in, const int* in_sizes, int n_in,
                              void* d_out, int out_size) {
    const float* x  = (const float*)d_in[0];
    const float* Wq = (const float*)d_in[1];
    const float* Wk = (const float*)d_in[2];
    const float* Wv = (const float*)d_in[3];
    float* out = (float*)d_out;

    qkv_kernel<<<(BB * TT) / 8, 256>>>(x, Wq, Wk, Wv);

    dim3 grid(TT / MTILE, SPLITS, BB);
    attn_partial_kernel<<<grid, 64>>>();

    attn_combine_kernel<<<(BB * TT) / 4, 128>>>(out);
}